// round 1
// baseline (speedup 1.0000x reference)
#include <cuda_runtime.h>

// Attn_Pred_Model: out[slice][s][b] =
//   ( sum_{i=0..7} alpha*beta^i * x[slice][s-1-i][b] + pb_fwd[b]
//     + pb_bwd[((s>>6)-b) & 63] ) * mask(s,b)
// mask(s,b) = 1 iff s >= max(128, 64*(b+1))   (constant within 64-row bands)
//
// Shapes: slices = 16*16 = 256, S = 4096, B = 64 (fp32).
// Pure HBM-streaming: 256MB in + 256MB out. Each x element read exactly once
// via an 8-deep per-thread rolling register window.

#define S_DIM   4096
#define B_DIM   64
#define SLICES  256
#define PAST    8
#define CHUNK   256              // rows per thread
#define N_CHUNK (S_DIM / CHUNK)  // 16

__global__ __launch_bounds__(128)
void attn_pred_kernel(const float* __restrict__ x,
                      const float* __restrict__ pb_fwd,
                      const float* __restrict__ pb_bwd,
                      const float* __restrict__ alpha_p,
                      const float* __restrict__ beta_p,
                      float* __restrict__ out)
{
    const int t     = blockIdx.x * blockDim.x + threadIdx.x;
    const int tb    = t & 31;        // float2 lane: columns b0=2*tb, b1=2*tb+1
    const int rest  = t >> 5;
    const int chunk = rest & (N_CHUNK - 1);
    const int slice = rest >> 4;     // rest / N_CHUNK

    // decay coefficients c[i] = alpha * beta^i
    const float alpha = alpha_p[0];
    const float beta  = beta_p[0];
    float c[PAST];
    {
        float cv = alpha;
        #pragma unroll
        for (int i = 0; i < PAST; i++) { c[i] = cv; cv *= beta; }
    }

    const int b0 = 2 * tb;
    const int b1 = b0 + 1;
    const float pf0 = __ldg(&pb_fwd[b0]);
    const float pf1 = __ldg(&pb_fwd[b1]);
    // mask thresholds (multiples of 64)
    const int thr0 = ((b0 + 1) * 64 < 128) ? 128 : (b0 + 1) * 64;
    const int thr1 = (b1 + 1) * 64;  // b1 >= 1 so already >= 128

    const size_t slice_off = (size_t)slice * S_DIM * (B_DIM / 2); // float2 units
    const float2* __restrict__ xin  = (const float2*)x  + slice_off + tb;
    float2*       __restrict__ xout = (float2*)out      + slice_off + tb;

    const int s0 = chunk * CHUNK;

    // rolling window: w[i] = x[s-1-i] for current s (= s0 at start)
    float2 w[PAST];
    #pragma unroll
    for (int i = 0; i < PAST; i++) {
        const int sr = s0 - 1 - i;
        w[i] = (sr >= 0) ? xin[(size_t)sr * 32] : make_float2(0.f, 0.f);
    }

    #pragma unroll
    for (int band = 0; band < CHUNK / 64; band++) {
        const int q = (s0 >> 6) + band;          // bucket row index, constant in band
        const float bias0 = pf0 + __ldg(&pb_bwd[(q - b0) & 63]);
        const float bias1 = pf1 + __ldg(&pb_bwd[(q - b1) & 63]);
        const float m0 = (q * 64 >= thr0) ? 1.f : 0.f;
        const float m1 = (q * 64 >= thr1) ? 1.f : 0.f;
        const int sbase = q * 64;

        #pragma unroll 8   // depth == PAST so window shift is free register rotation
        for (int r = 0; r < 64; r++) {
            const int s = sbase + r;
            const float2 cur = xin[(size_t)s * 32];

            float ax = 0.f, ay = 0.f;
            #pragma unroll
            for (int i = 0; i < PAST; i++) {
                ax = fmaf(c[i], w[i].x, ax);
                ay = fmaf(c[i], w[i].y, ay);
            }

            float2 o;
            o.x = m0 * (ax + bias0);
            o.y = m1 * (ay + bias1);
            xout[(size_t)s * 32] = o;

            #pragma unroll
            for (int i = PAST - 1; i > 0; i--) w[i] = w[i - 1];
            w[0] = cur;
        }
    }
}

extern "C" void kernel_launch(void* const* d_in, const int* in_sizes, int n_in,
                              void* d_out, int out_size)
{
    // metadata order: x, pb_fwd, pb_bwd, alpha, beta, arange2, mask
    const float* x      = (const float*)d_in[0];
    const float* pb_fwd = (const float*)d_in[1];
    const float* pb_bwd = (const float*)d_in[2];
    const float* alpha  = (const float*)d_in[3];
    const float* beta   = (const float*)d_in[4];
    // arange2 (d_in[5]) and mask (d_in[6]) are reproduced analytically in-kernel.

    const int total_threads = SLICES * N_CHUNK * 32;  // 131072
    const int block = 128;
    attn_pred_kernel<<<total_threads / block, block>>>(
        x, pb_fwd, pb_bwd, alpha, beta, (float*)d_out);
}

// round 3
// speedup vs baseline: 1.1713x; 1.1713x over previous
#include <cuda_runtime.h>

// Attn_Pred_Model: out[slice][s][b] =
//   ( sum_{i=0..7} alpha*beta^i * x[slice][s-1-i][b] + pb_fwd[b]
//     + pb_bwd[((s>>6)-b) & 63] ) * mask(s,b)
// mask(s,b) = 1 iff s >= max(128, 64*(b+1))  (band-constant, band = 64 rows)
//
// Key traffic optimization: mask zeroes the triangular region s < 64*max(2,b+1)
// (~51% of output). x[s,b] only feeds out[s+1..s+8, b], so x[s,b] is never
// needed when s + 8 < 64*qact(b). Those loads are predicated off per-lane,
// eliminating ~49% of read traffic at DRAM sector granularity.
// Writes (256MB) are mandatory: d_out is poisoned and zeros must be stored.

#define S_DIM   4096
#define B_DIM   64
#define SLICES  256
#define PAST    8
#define CHUNK   256              // rows per thread
#define N_CHUNK (S_DIM / CHUNK)  // 16

__global__ __launch_bounds__(128)
void attn_pred_kernel(const float* __restrict__ x,
                      const float* __restrict__ pb_fwd,
                      const float* __restrict__ pb_bwd,
                      const float* __restrict__ alpha_p,
                      const float* __restrict__ beta_p,
                      float* __restrict__ out)
{
    const int t     = blockIdx.x * blockDim.x + threadIdx.x;
    const int tb    = t & 31;        // float2 lane: columns b0=2*tb, b1=2*tb+1
    const int rest  = t >> 5;
    const int chunk = rest & (N_CHUNK - 1);
    const int slice = rest >> 4;     // rest / N_CHUNK

    // decay coefficients c[i] = alpha * beta^i
    const float alpha = alpha_p[0];
    const float beta  = beta_p[0];
    float c[PAST];
    {
        float cv = alpha;
        #pragma unroll
        for (int i = 0; i < PAST; i++) { c[i] = cv; cv *= beta; }
    }

    const int b0 = 2 * tb;
    const int b1 = b0 + 1;
    const float pf0 = __ldg(&pb_fwd[b0]);
    const float pf1 = __ldg(&pb_fwd[b1]);

    // first active band per column: active iff s >= 64*qact
    const int qact0 = (b0 + 1 < 2) ? 2 : (b0 + 1);   // max(2, b0+1)
    const int qact1 = b1 + 1;                        // b1 >= 1 so already >= 2
    // load needed iff s + 8 >= 64*qact0  (x[s] feeds out[s+1..s+8]; col b1
    // activates later than b0, so b0's predicate covers the float2 pair)
    const int ld_thresh = (qact0 << 6) - 8;

    const size_t slice_off = (size_t)slice * S_DIM * (B_DIM / 2); // float2 units
    const float2* __restrict__ xin  = (const float2*)x  + slice_off + tb;
    float2*       __restrict__ xout = (float2*)out      + slice_off + tb;

    const int s0 = chunk * CHUNK;

    // rolling window: w[i] = x[s-1-i] for current s (= s0 at start)
    float2 w[PAST];
    #pragma unroll
    for (int i = 0; i < PAST; i++) {
        const int sr = s0 - 1 - i;
        w[i] = (sr >= 0 && sr >= ld_thresh) ? xin[(size_t)sr * 32]
                                            : make_float2(0.f, 0.f);
    }

    #pragma unroll
    for (int band = 0; band < CHUNK / 64; band++) {
        const int q = (s0 >> 6) + band;          // bucket row index, constant in band
        const float bias0 = pf0 + __ldg(&pb_bwd[(q - b0) & 63]);
        const float bias1 = pf1 + __ldg(&pb_bwd[(q - b1) & 63]);
        const float m0 = (q >= qact0) ? 1.f : 0.f;
        const float m1 = (q >= qact1) ? 1.f : 0.f;
        const int sbase = q * 64;

        #pragma unroll 8   // depth == PAST so window shift is free register rotation
        for (int r = 0; r < 64; r++) {
            const int s = sbase + r;
            // predicated load: skipped lanes fetch nothing from DRAM
            const float2 cur = (s >= ld_thresh) ? xin[(size_t)s * 32]
                                                : make_float2(0.f, 0.f);

            float ax = 0.f, ay = 0.f;
            #pragma unroll
            for (int i = 0; i < PAST; i++) {
                ax = fmaf(c[i], w[i].x, ax);
                ay = fmaf(c[i], w[i].y, ay);
            }

            float2 o;
            o.x = m0 * (ax + bias0);
            o.y = m1 * (ay + bias1);
            xout[(size_t)s * 32] = o;

            #pragma unroll
            for (int i = PAST - 1; i > 0; i--) w[i] = w[i - 1];
            w[0] = cur;
        }
    }
}

extern "C" void kernel_launch(void* const* d_in, const int* in_sizes, int n_in,
                              void* d_out, int out_size)
{
    // metadata order: x, pb_fwd, pb_bwd, alpha, beta, arange2, mask
    const float* x      = (const float*)d_in[0];
    const float* pb_fwd = (const float*)d_in[1];
    const float* pb_bwd = (const float*)d_in[2];
    const float* alpha  = (const float*)d_in[3];
    const float* beta   = (const float*)d_in[4];
    // arange2 (d_in[5]) and mask (d_in[6]) are reproduced analytically in-kernel.

    const int total_threads = SLICES * N_CHUNK * 32;  // 131072
    const int block = 128;
    attn_pred_kernel<<<total_threads / block, block>>>(
        x, pb_fwd, pb_bwd, alpha, beta, (float*)d_out);
}